// round 10
// baseline (speedup 1.0000x reference)
#include <cuda_runtime.h>
#include <cuda_fp16.h>
#include <cstdint>

#define NN   32
#define WH   4096
#define CC   256
#define SCALE 0.0625f      // 1/sqrt(256)
#define BSCALE 64.0f       // pre-scale on B to keep folded ca*W in fp16 normal range
#define INV_BSCALE 0.015625f
#define GRIDN 152          // persistent CTAs (GB300: 152 SMs)
#define NITEMS 1024        // 32 mtiles x 32 batches

// Scratch (device globals — no allocations allowed)
__device__ float g_q[NN * CC];
__device__ float g_partS[NN * 16 * CC];
__device__ float g_palog[NN * WH];
__device__ float g_ca[NN * CC];
__device__ float g_pa[NN * WH];
__device__ __align__(16) unsigned short g_Ah[(size_t)NN * WH * CC]; // fp16(inputs)
__device__ __align__(16) unsigned short g_Bh[NN * CC * CC];         // per-batch 64*ca*W

// ---------------------------------------------------------------------------
// Helpers (baseline PTX — plain sm_103 target)
// ---------------------------------------------------------------------------
__device__ __forceinline__ void ldm4(uint32_t* r, uint32_t addr) {
    asm volatile("ldmatrix.sync.aligned.m8n8.x4.shared.b16 {%0,%1,%2,%3}, [%4];"
                 : "=r"(r[0]), "=r"(r[1]), "=r"(r[2]), "=r"(r[3]) : "r"(addr));
}
__device__ __forceinline__ void mma_f16(float* c, const uint32_t* a,
                                        uint32_t b0, uint32_t b1) {
    asm volatile(
        "mma.sync.aligned.m16n8k16.row.col.f32.f16.f16.f32 "
        "{%0,%1,%2,%3}, {%4,%5,%6,%7}, {%8,%9}, {%0,%1,%2,%3};"
        : "+f"(c[0]), "+f"(c[1]), "+f"(c[2]), "+f"(c[3])
        : "r"(a[0]), "r"(a[1]), "r"(a[2]), "r"(a[3]), "r"(b0), "r"(b1));
}
__device__ __forceinline__ uint32_t pack_h2(float a, float b) {
    __half2 t = __floats2half2_rn(a, b);
    return *reinterpret_cast<uint32_t*>(&t);
}
__device__ __forceinline__ void cp16(uint32_t dst, const void* src) {
    asm volatile("cp.async.cg.shared.global [%0], [%1], 16;"
                 :: "r"(dst), "l"(src) : "memory");
}

// ---------------------------------------------------------------------------
// K1: q[n,c] = leaky_relu_0.3( style @ w_dense )
// ---------------------------------------------------------------------------
__global__ void k_q(const float* __restrict__ style, const float* __restrict__ wd) {
    int n = blockIdx.x, c = threadIdx.x;
    __shared__ float s[CC];
    s[c] = style[n * CC + c];
    __syncthreads();
    float acc = 0.f;
#pragma unroll 8
    for (int k = 0; k < CC; k++) acc = fmaf(s[k], wd[k * CC + c], acc);
    g_q[n * CC + c] = acc > 0.f ? acc : 0.3f * acc;
}

// ---------------------------------------------------------------------------
// K2: one pass over inputs: pa_logits + partial column sums + fp16 copy of A
// ---------------------------------------------------------------------------
__global__ void k_pa_colsum(const float* __restrict__ in) {
    int n = blockIdx.y, chunk = blockIdx.x;
    int tid = threadIdx.x, lane = tid & 31, w = tid >> 5;

    const float4* q4 = reinterpret_cast<const float4*>(g_q + (size_t)n * CC);
    float4 qa = q4[lane * 2], qb = q4[lane * 2 + 1];

    float4 cs0 = {0.f, 0.f, 0.f, 0.f}, cs1 = {0.f, 0.f, 0.f, 0.f};
    int pbase = chunk * 256 + w * 32;
    const float4* base4 =
        reinterpret_cast<const float4*>(in + ((size_t)n * WH + pbase) * CC);

    for (int i = 0; i < 32; i++) {
        const float4* r = base4 + (size_t)i * (CC / 4);
        float4 v0 = r[lane * 2], v1 = r[lane * 2 + 1];
        float d = v0.x * qa.x + v0.y * qa.y + v0.z * qa.z + v0.w * qa.w
                + v1.x * qb.x + v1.y * qb.y + v1.z * qb.z + v1.w * qb.w;
        cs0.x += v0.x; cs0.y += v0.y; cs0.z += v0.z; cs0.w += v0.w;
        cs1.x += v1.x; cs1.y += v1.y; cs1.z += v1.z; cs1.w += v1.w;
        // fp16 copy of the input (A operand for the conv GEMM)
        uint4 hc;
        hc.x = pack_h2(v0.x, v0.y); hc.y = pack_h2(v0.z, v0.w);
        hc.z = pack_h2(v1.x, v1.y); hc.w = pack_h2(v1.z, v1.w);
        *reinterpret_cast<uint4*>(
            g_Ah + ((size_t)n * WH + pbase + i) * CC + lane * 8) = hc;
#pragma unroll
        for (int o = 16; o; o >>= 1) d += __shfl_xor_sync(0xffffffffu, d, o);
        if (lane == 0) g_palog[(size_t)n * WH + pbase + i] = d * SCALE;
    }

    __shared__ float sm[8 * CC];
    float* smw = sm + w * CC + lane * 8;
    smw[0] = cs0.x; smw[1] = cs0.y; smw[2] = cs0.z; smw[3] = cs0.w;
    smw[4] = cs1.x; smw[5] = cs1.y; smw[6] = cs1.z; smw[7] = cs1.w;
    __syncthreads();
    float ssum = 0.f;
#pragma unroll
    for (int ww = 0; ww < 8; ww++) ssum += sm[ww * CC + tid];
    g_partS[((size_t)n * 16 + chunk) * CC + tid] = ssum;
}

// ---------------------------------------------------------------------------
// K3 (fused): blocks 0..31 -> channel softmax; 32..63 -> position softmax
// ---------------------------------------------------------------------------
__global__ void k_soft() {
    int b = blockIdx.x, tid = threadIdx.x;
    __shared__ float red[256];
    if (b < NN) {
        int n = b;
        float S = 0.f;
#pragma unroll
        for (int k = 0; k < 16; k++) S += g_partS[((size_t)n * 16 + k) * CC + tid];
        float logit = S * g_q[n * CC + tid] * SCALE;
        red[tid] = logit; __syncthreads();
        for (int s = 128; s; s >>= 1) {
            if (tid < s) red[tid] = fmaxf(red[tid], red[tid + s]);
            __syncthreads();
        }
        float m = red[0]; __syncthreads();
        float e = expf(logit - m);
        red[tid] = e; __syncthreads();
        for (int s = 128; s; s >>= 1) {
            if (tid < s) red[tid] += red[tid + s];
            __syncthreads();
        }
        g_ca[n * CC + tid] = e / red[0];
    } else {
        int n = b - NN;
        float v[16];
        float m = -1e30f;
#pragma unroll
        for (int i = 0; i < 16; i++) {
            v[i] = g_palog[(size_t)n * WH + i * 256 + tid];
            m = fmaxf(m, v[i]);
        }
        red[tid] = m; __syncthreads();
        for (int s = 128; s; s >>= 1) {
            if (tid < s) red[tid] = fmaxf(red[tid], red[tid + s]);
            __syncthreads();
        }
        m = red[0]; __syncthreads();
        float sum = 0.f;
#pragma unroll
        for (int i = 0; i < 16; i++) { v[i] = expf(v[i] - m); sum += v[i]; }
        red[tid] = sum; __syncthreads();
        for (int s = 128; s; s >>= 1) {
            if (tid < s) red[tid] += red[tid + s];
            __syncthreads();
        }
        float r = 1.f / red[0];
#pragma unroll
        for (int i = 0; i < 16; i++)
            g_pa[(size_t)n * WH + i * 256 + tid] = v[i] * r;
    }
}

// ---------------------------------------------------------------------------
// K_prepB: per-batch B_eff[co][ci] = fp16( 64 * ca[n][ci] * W[ci][co] ).
// grid=(32 ci-blocks of 8, 32 n), block=256 (t = co). 4x more blocks than
// before — was latency-bound at 7.6us with only 256 blocks.
// ---------------------------------------------------------------------------
__global__ void k_prepB(const float* __restrict__ wc) {
    int cb = blockIdx.x, n = blockIdx.y, t = threadIdx.x;
    int ci0 = cb * 8;
    const float* cap = g_ca + n * CC + ci0;
    uint32_t hi[4];
#pragma unroll
    for (int j = 0; j < 8; j += 2) {
        float v0 = BSCALE * cap[j]     * wc[(size_t)(ci0 + j) * CC + t];
        float v1 = BSCALE * cap[j + 1] * wc[(size_t)(ci0 + j + 1) * CC + t];
        hi[j >> 1] = pack_h2(v0, v1);
    }
    *reinterpret_cast<uint4*>(g_Bh + ((size_t)n * CC + t) * CC + ci0) =
        make_uint4(hi[0], hi[1], hi[2], hi[3]);
}

// ---------------------------------------------------------------------------
// K4: persistent HMMA fp16 GEMM. 152 CTAs loop over 1024 items (mtile,batch).
// Per item: 2 K-chunks of 128, two buffers; next item's chunks load while the
// current item computes -> first-chunk exposure paid once per CTA, not per item.
// Epilogue: leaky0.1 * pa/64.
// ---------------------------------------------------------------------------
#define RS     272                   // smem row stride bytes (128 halves + 8 pad)
#define A_OFF  0
#define B_OFF  34816                 // 128 * 272
#define BUFB   104448                // A (34816) + B (256*272=69632)
#define SMEMB  (2 * BUFB)            // 208896

__global__ void __launch_bounds__(256, 1)
k_conv_mma(float* __restrict__ out) {
    extern __shared__ char smem[];
    const uint32_t sb = (uint32_t)__cvta_generic_to_shared(smem);
    const int tid = threadIdx.x, lane = tid & 31, wid = tid >> 5;
    const int warp_m = (wid & 1) * 64, warp_n = (wid >> 1) * 64;
    const int q = lane >> 3;

    const uint32_t aBase = sb + A_OFF
        + (uint32_t)(warp_m + (lane & 7) + ((q & 1) << 3)) * RS + ((q >> 1) << 4);
    const uint32_t bBase = sb + B_OFF
        + (uint32_t)(warp_n + (lane & 7) + ((q >> 1) << 3)) * RS + ((q & 1) << 4);

    // Issue one chunk (c=0/1) of one item into buffer buf.
    auto issue = [&](int item, int c, int buf) {
        const int nb = item >> 5, m0 = (item & 31) * 128;
        const unsigned short* Asrc = g_Ah + ((size_t)nb * WH + m0) * CC;
        const unsigned short* Bsrc = g_Bh + (size_t)nb * CC * CC;
        uint32_t d = sb + (uint32_t)buf * BUFB;
#pragma unroll
        for (int j = 0; j < 8; j++) {
            int o = tid + 256 * j, row = o >> 4, seg = o & 15;
            cp16(d + A_OFF + row * RS + seg * 16,
                 Asrc + (size_t)row * CC + c * 128 + seg * 8);
        }
#pragma unroll
        for (int j = 0; j < 16; j++) {
            int o = tid + 256 * j, row = o >> 4, seg = o & 15;
            cp16(d + B_OFF + row * RS + seg * 16,
                 Bsrc + (size_t)row * CC + c * 128 + seg * 8);
        }
        asm volatile("cp.async.commit_group;" ::: "memory");
    };

    float acc[4][8][4];

    auto compute = [&](int buf) {
        const uint32_t bo = (uint32_t)buf * BUFB;
#pragma unroll
        for (int ks = 0; ks < 8; ks++) {
            const uint32_t ko = bo + ks * 32;
            uint32_t ah[4][4];
#pragma unroll
            for (int mt = 0; mt < 4; mt++)
                ldm4(ah[mt], aBase + ko + mt * 16 * RS);
#pragma unroll
            for (int p = 0; p < 4; p++) {
                uint32_t bh[4];
                ldm4(bh, bBase + ko + p * 16 * RS);
#pragma unroll
                for (int mt = 0; mt < 4; mt++) {
                    mma_f16(acc[mt][2 * p],     ah[mt], bh[0], bh[1]);
                    mma_f16(acc[mt][2 * p + 1], ah[mt], bh[2], bh[3]);
                }
            }
        }
    };

    int it = blockIdx.x;
    if (it >= NITEMS) return;
    issue(it, 0, 0);
    issue(it, 1, 1);

    const int g = lane >> 2, tg = lane & 3;

    while (true) {
        const int next = it + GRIDN;
        const bool hn = next < NITEMS;

#pragma unroll
        for (int i = 0; i < 4; i++)
#pragma unroll
            for (int j = 0; j < 8; j++)
#pragma unroll
                for (int t = 0; t < 4; t++) acc[i][j][t] = 0.f;

        // --- chunk 0 ---
        asm volatile("cp.async.wait_group 1;" ::: "memory");
        __syncthreads();
        compute(0);
        __syncthreads();                 // all warps done reading buf0
        if (hn) issue(next, 0, 0);

        // --- chunk 1 ---
        if (hn) asm volatile("cp.async.wait_group 1;" ::: "memory");
        else    asm volatile("cp.async.wait_group 0;" ::: "memory");
        __syncthreads();
        compute(1);
        if (hn) {
            __syncthreads();             // all warps done reading buf1
            issue(next, 1, 1);
        }

        // --- epilogue: leaky0.1 then * pa/64 ---
        const int nb = it >> 5, m0 = (it & 31) * 128;
#pragma unroll
        for (int mt = 0; mt < 4; mt++) {
            int r0 = m0 + warp_m + mt * 16 + g;
            float pa0 = g_pa[(size_t)nb * WH + r0] * INV_BSCALE;
            float pa1 = g_pa[(size_t)nb * WH + r0 + 8] * INV_BSCALE;
            float* o0 = out + ((size_t)nb * WH + r0) * CC + warp_n + tg * 2;
            float* o1 = o0 + 8 * CC;
#pragma unroll
            for (int nt = 0; nt < 8; nt++) {
                float v0 = acc[mt][nt][0], v1 = acc[mt][nt][1];
                float v2 = acc[mt][nt][2], v3 = acc[mt][nt][3];
                v0 = (v0 > 0.f ? v0 : 0.1f * v0) * pa0;
                v1 = (v1 > 0.f ? v1 : 0.1f * v1) * pa0;
                v2 = (v2 > 0.f ? v2 : 0.1f * v2) * pa1;
                v3 = (v3 > 0.f ? v3 : 0.1f * v3) * pa1;
                *reinterpret_cast<float2*>(o0 + nt * 8) = make_float2(v0, v1);
                *reinterpret_cast<float2*>(o1 + nt * 8) = make_float2(v2, v3);
            }
        }

        if (!hn) break;
        it = next;
    }
}

// ---------------------------------------------------------------------------
extern "C" void kernel_launch(void* const* d_in, const int* in_sizes, int n_in,
                              void* d_out, int out_size) {
    const float* in    = (const float*)d_in[0];  // [32,64,64,256]
    const float* style = (const float*)d_in[1];  // [32,256]
    const float* wd    = (const float*)d_in[2];  // [256,256]
    const float* wc    = (const float*)d_in[3];  // [1,1,256,256] -> [ci][co]
    float* out = (float*)d_out;

    static bool attr_set = false;
    if (!attr_set) {
        cudaFuncSetAttribute(k_conv_mma,
                             cudaFuncAttributeMaxDynamicSharedMemorySize, SMEMB);
        attr_set = true;
    }

    k_q<<<NN, CC>>>(style, wd);
    k_pa_colsum<<<dim3(16, NN), 256>>>(in);
    k_soft<<<2 * NN, 256>>>();
    k_prepB<<<dim3(32, NN), 256>>>(wc);
    k_conv_mma<<<GRIDN, 256, SMEMB>>>(out);
}

// round 12
// speedup vs baseline: 1.0655x; 1.0655x over previous
#include <cuda_runtime.h>
#include <cuda_fp16.h>
#include <cstdint>

#define NN   32
#define WH   4096
#define CC   256
#define SCALE 0.0625f      // 1/sqrt(256)
#define BSCALE 64.0f       // pre-scale on B to keep folded ca*W in fp16 normal range
#define INV_BSCALE 0.015625f

// Scratch (device globals — no allocations allowed)
__device__ float g_q[NN * CC];
__device__ float g_partS[NN * 16 * CC];
__device__ float g_palog[NN * WH];
__device__ float g_ca[NN * CC];
__device__ float g_pa[NN * WH];
__device__ __align__(16) unsigned short g_Ah[(size_t)NN * WH * CC]; // fp16(inputs)
__device__ __align__(16) unsigned short g_Bh[NN * CC * CC];         // per-batch 64*ca*W

// ---------------------------------------------------------------------------
// Helpers (baseline PTX — plain sm_103 target)
// ---------------------------------------------------------------------------
__device__ __forceinline__ void ldm4(uint32_t* r, uint32_t addr) {
    asm volatile("ldmatrix.sync.aligned.m8n8.x4.shared.b16 {%0,%1,%2,%3}, [%4];"
                 : "=r"(r[0]), "=r"(r[1]), "=r"(r[2]), "=r"(r[3]) : "r"(addr));
}
__device__ __forceinline__ void mma_f16(float* c, const uint32_t* a,
                                        uint32_t b0, uint32_t b1) {
    asm volatile(
        "mma.sync.aligned.m16n8k16.row.col.f32.f16.f16.f32 "
        "{%0,%1,%2,%3}, {%4,%5,%6,%7}, {%8,%9}, {%0,%1,%2,%3};"
        : "+f"(c[0]), "+f"(c[1]), "+f"(c[2]), "+f"(c[3])
        : "r"(a[0]), "r"(a[1]), "r"(a[2]), "r"(a[3]), "r"(b0), "r"(b1));
}
__device__ __forceinline__ uint32_t pack_h2(float a, float b) {
    __half2 t = __floats2half2_rn(a, b);
    return *reinterpret_cast<uint32_t*>(&t);
}
__device__ __forceinline__ void cp16(uint32_t dst, const void* src) {
    asm volatile("cp.async.cg.shared.global [%0], [%1], 16;"
                 :: "r"(dst), "l"(src) : "memory");
}

// ---------------------------------------------------------------------------
// K1: q[n,c] = leaky_relu_0.3( style @ w_dense )
// ---------------------------------------------------------------------------
__global__ void k_q(const float* __restrict__ style, const float* __restrict__ wd) {
    int n = blockIdx.x, c = threadIdx.x;
    __shared__ float s[CC];
    s[c] = style[n * CC + c];
    __syncthreads();
    float acc = 0.f;
#pragma unroll 8
    for (int k = 0; k < CC; k++) acc = fmaf(s[k], wd[k * CC + c], acc);
    g_q[n * CC + c] = acc > 0.f ? acc : 0.3f * acc;
}

// ---------------------------------------------------------------------------
// K2: one pass over inputs: pa_logits + partial column sums + fp16 copy of A
// ---------------------------------------------------------------------------
__global__ void k_pa_colsum(const float* __restrict__ in) {
    int n = blockIdx.y, chunk = blockIdx.x;
    int tid = threadIdx.x, lane = tid & 31, w = tid >> 5;

    const float4* q4 = reinterpret_cast<const float4*>(g_q + (size_t)n * CC);
    float4 qa = q4[lane * 2], qb = q4[lane * 2 + 1];

    float4 cs0 = {0.f, 0.f, 0.f, 0.f}, cs1 = {0.f, 0.f, 0.f, 0.f};
    int pbase = chunk * 256 + w * 32;
    const float4* base4 =
        reinterpret_cast<const float4*>(in + ((size_t)n * WH + pbase) * CC);

    for (int i = 0; i < 32; i++) {
        const float4* r = base4 + (size_t)i * (CC / 4);
        float4 v0 = r[lane * 2], v1 = r[lane * 2 + 1];
        float d = v0.x * qa.x + v0.y * qa.y + v0.z * qa.z + v0.w * qa.w
                + v1.x * qb.x + v1.y * qb.y + v1.z * qb.z + v1.w * qb.w;
        cs0.x += v0.x; cs0.y += v0.y; cs0.z += v0.z; cs0.w += v0.w;
        cs1.x += v1.x; cs1.y += v1.y; cs1.z += v1.z; cs1.w += v1.w;
        // fp16 copy of the input (A operand for the conv GEMM)
        uint4 hc;
        hc.x = pack_h2(v0.x, v0.y); hc.y = pack_h2(v0.z, v0.w);
        hc.z = pack_h2(v1.x, v1.y); hc.w = pack_h2(v1.z, v1.w);
        *reinterpret_cast<uint4*>(
            g_Ah + ((size_t)n * WH + pbase + i) * CC + lane * 8) = hc;
#pragma unroll
        for (int o = 16; o; o >>= 1) d += __shfl_xor_sync(0xffffffffu, d, o);
        if (lane == 0) g_palog[(size_t)n * WH + pbase + i] = d * SCALE;
    }

    __shared__ float sm[8 * CC];
    float* smw = sm + w * CC + lane * 8;
    smw[0] = cs0.x; smw[1] = cs0.y; smw[2] = cs0.z; smw[3] = cs0.w;
    smw[4] = cs1.x; smw[5] = cs1.y; smw[6] = cs1.z; smw[7] = cs1.w;
    __syncthreads();
    float ssum = 0.f;
#pragma unroll
    for (int ww = 0; ww < 8; ww++) ssum += sm[ww * CC + tid];
    g_partS[((size_t)n * 16 + chunk) * CC + tid] = ssum;
}

// ---------------------------------------------------------------------------
// K3 (fused): blocks 0..31 -> channel softmax; 32..63 -> position softmax
// ---------------------------------------------------------------------------
__global__ void k_soft() {
    int b = blockIdx.x, tid = threadIdx.x;
    __shared__ float red[256];
    if (b < NN) {
        int n = b;
        float S = 0.f;
#pragma unroll
        for (int k = 0; k < 16; k++) S += g_partS[((size_t)n * 16 + k) * CC + tid];
        float logit = S * g_q[n * CC + tid] * SCALE;
        red[tid] = logit; __syncthreads();
        for (int s = 128; s; s >>= 1) {
            if (tid < s) red[tid] = fmaxf(red[tid], red[tid + s]);
            __syncthreads();
        }
        float m = red[0]; __syncthreads();
        float e = expf(logit - m);
        red[tid] = e; __syncthreads();
        for (int s = 128; s; s >>= 1) {
            if (tid < s) red[tid] += red[tid + s];
            __syncthreads();
        }
        g_ca[n * CC + tid] = e / red[0];
    } else {
        int n = b - NN;
        float v[16];
        float m = -1e30f;
#pragma unroll
        for (int i = 0; i < 16; i++) {
            v[i] = g_palog[(size_t)n * WH + i * 256 + tid];
            m = fmaxf(m, v[i]);
        }
        red[tid] = m; __syncthreads();
        for (int s = 128; s; s >>= 1) {
            if (tid < s) red[tid] = fmaxf(red[tid], red[tid + s]);
            __syncthreads();
        }
        m = red[0]; __syncthreads();
        float sum = 0.f;
#pragma unroll
        for (int i = 0; i < 16; i++) { v[i] = expf(v[i] - m); sum += v[i]; }
        red[tid] = sum; __syncthreads();
        for (int s = 128; s; s >>= 1) {
            if (tid < s) red[tid] += red[tid + s];
            __syncthreads();
        }
        float r = 1.f / red[0];
#pragma unroll
        for (int i = 0; i < 16; i++)
            g_pa[(size_t)n * WH + i * 256 + tid] = v[i] * r;
    }
}

// ---------------------------------------------------------------------------
// K_prepB: per-batch B_eff[co][ci] = fp16( 64 * ca[n][ci] * W[ci][co] ).
// grid=(32 ci-blocks of 8, 32 n), block=256 (t = co).
// ---------------------------------------------------------------------------
__global__ void k_prepB(const float* __restrict__ wc) {
    int cb = blockIdx.x, n = blockIdx.y, t = threadIdx.x;
    int ci0 = cb * 8;
    const float* cap = g_ca + n * CC + ci0;
    uint32_t hi[4];
#pragma unroll
    for (int j = 0; j < 8; j += 2) {
        float v0 = BSCALE * cap[j]     * wc[(size_t)(ci0 + j) * CC + t];
        float v1 = BSCALE * cap[j + 1] * wc[(size_t)(ci0 + j + 1) * CC + t];
        hi[j >> 1] = pack_h2(v0, v1);
    }
    *reinterpret_cast<uint4*>(g_Bh + ((size_t)n * CC + t) * CC + ci0) =
        make_uint4(hi[0], hi[1], hi[2], hi[3]);
}

// ---------------------------------------------------------------------------
// K4: HMMA fp16 GEMM, CTA tile 128x128, warp tile 32x64 (acc=64 regs),
// 2 CTAs/SM (4 warps/SMSP), regs ~115 <= 128 cap -> no spills.
// cp.async double-buffered K-chunks of 64 (8 segs/row of 16B — R11 loaded
// only 4, leaving half of smem uninitialized -> NaN; fixed here).
// Epilogue: leaky0.1 * pa/64. grid=(32 mtiles, 2 ntiles, 32 batch), block=256.
// ---------------------------------------------------------------------------
#define RS     144                   // smem row stride bytes (64 halves + 8 pad)
#define A_OFF  0
#define B_OFF  18432                 // 128 * 144
#define BUFB   36864                 // A + B
#define SMEMB  (2 * BUFB)            // 73728 per CTA -> 147456 per SM @2 CTAs

__global__ void __launch_bounds__(256, 2)
k_conv_mma(float* __restrict__ out) {
    extern __shared__ char smem[];
    const uint32_t sb = (uint32_t)__cvta_generic_to_shared(smem);
    const int tid = threadIdx.x, lane = tid & 31, wid = tid >> 5;
    const int nb = blockIdx.z;
    const int m0 = blockIdx.x * 128;
    const int n0 = blockIdx.y * 128;
    const int warp_m = (wid & 3) * 32, warp_n = (wid >> 2) * 64;
    const int q = lane >> 3;

    const uint32_t aBase = sb + A_OFF
        + (uint32_t)(warp_m + (lane & 7) + ((q & 1) << 3)) * RS + ((q >> 1) << 4);
    const uint32_t bBase = sb + B_OFF
        + (uint32_t)(warp_n + (lane & 7) + ((q >> 1) << 3)) * RS + ((q & 1) << 4);

    const unsigned short* Asrc = g_Ah + ((size_t)nb * WH + m0) * CC;
    const unsigned short* Bsrc = g_Bh + ((size_t)nb * CC + n0) * CC;

    float acc[2][8][4];
#pragma unroll
    for (int i = 0; i < 2; i++)
#pragma unroll
        for (int j = 0; j < 8; j++)
#pragma unroll
            for (int t = 0; t < 4; t++) acc[i][j][t] = 0.f;

    // chunk c covers k in [c*64, c*64+64):
    // A and B each 128 rows x 8 segs of 16B = 1024 cp16 per operand.
    auto issue = [&](int c, int buf) {
        uint32_t d = sb + (uint32_t)buf * BUFB;
#pragma unroll
        for (int j = 0; j < 4; j++) {
            int o = tid + 256 * j, row = o >> 3, seg = o & 7;
            cp16(d + A_OFF + row * RS + seg * 16,
                 Asrc + (size_t)row * CC + c * 64 + seg * 8);
        }
#pragma unroll
        for (int j = 0; j < 4; j++) {
            int o = tid + 256 * j, row = o >> 3, seg = o & 7;
            cp16(d + B_OFF + row * RS + seg * 16,
                 Bsrc + (size_t)row * CC + c * 64 + seg * 8);
        }
        asm volatile("cp.async.commit_group;" ::: "memory");
    };

    issue(0, 0);
    for (int c = 0; c < 4; c++) {
        const int buf = c & 1;
        if (c < 3) {
            issue(c + 1, buf ^ 1);
            asm volatile("cp.async.wait_group 1;" ::: "memory");
        } else {
            asm volatile("cp.async.wait_group 0;" ::: "memory");
        }
        __syncthreads();
        const uint32_t bo = (uint32_t)buf * BUFB;
#pragma unroll
        for (int ks = 0; ks < 4; ks++) {
            const uint32_t ko = bo + ks * 32;
            uint32_t ah[2][4];
            ldm4(ah[0], aBase + ko);
            ldm4(ah[1], aBase + ko + 16 * RS);
#pragma unroll
            for (int p = 0; p < 4; p++) {
                uint32_t bh[4];
                ldm4(bh, bBase + ko + p * 16 * RS);
                mma_f16(acc[0][2 * p],     ah[0], bh[0], bh[1]);
                mma_f16(acc[0][2 * p + 1], ah[0], bh[2], bh[3]);
                mma_f16(acc[1][2 * p],     ah[1], bh[0], bh[1]);
                mma_f16(acc[1][2 * p + 1], ah[1], bh[2], bh[3]);
            }
        }
        __syncthreads();
    }

    // --- Epilogue: leaky0.1 then * pa/64 (undo BSCALE; leaky is +homogeneous) ---
    const int g = lane >> 2, tg = lane & 3;
#pragma unroll
    for (int mt = 0; mt < 2; mt++) {
        int r0 = m0 + warp_m + mt * 16 + g;
        float pa0 = g_pa[(size_t)nb * WH + r0] * INV_BSCALE;
        float pa1 = g_pa[(size_t)nb * WH + r0 + 8] * INV_BSCALE;
        float* o0 = out + ((size_t)nb * WH + r0) * CC + n0 + warp_n + tg * 2;
        float* o1 = o0 + 8 * CC;
#pragma unroll
        for (int nt = 0; nt < 8; nt++) {
            float v0 = acc[mt][nt][0], v1 = acc[mt][nt][1];
            float v2 = acc[mt][nt][2], v3 = acc[mt][nt][3];
            v0 = (v0 > 0.f ? v0 : 0.1f * v0) * pa0;
            v1 = (v1 > 0.f ? v1 : 0.1f * v1) * pa0;
            v2 = (v2 > 0.f ? v2 : 0.1f * v2) * pa1;
            v3 = (v3 > 0.f ? v3 : 0.1f * v3) * pa1;
            *reinterpret_cast<float2*>(o0 + nt * 8) = make_float2(v0, v1);
            *reinterpret_cast<float2*>(o1 + nt * 8) = make_float2(v2, v3);
        }
    }
}

// ---------------------------------------------------------------------------
extern "C" void kernel_launch(void* const* d_in, const int* in_sizes, int n_in,
                              void* d_out, int out_size) {
    const float* in    = (const float*)d_in[0];  // [32,64,64,256]
    const float* style = (const float*)d_in[1];  // [32,256]
    const float* wd    = (const float*)d_in[2];  // [256,256]
    const float* wc    = (const float*)d_in[3];  // [1,1,256,256] -> [ci][co]
    float* out = (float*)d_out;

    static bool attr_set = false;
    if (!attr_set) {
        cudaFuncSetAttribute(k_conv_mma,
                             cudaFuncAttributeMaxDynamicSharedMemorySize, SMEMB);
        attr_set = true;
    }

    k_q<<<NN, CC>>>(style, wd);
    k_pa_colsum<<<dim3(16, NN), 256>>>(in);
    k_soft<<<2 * NN, 256>>>();
    k_prepB<<<dim3(32, NN), 256>>>(wc);
    k_conv_mma<<<dim3(32, 2, NN), 256, SMEMB>>>(out);
}

// round 13
// speedup vs baseline: 1.0840x; 1.0173x over previous
#include <cuda_runtime.h>
#include <cuda_fp16.h>
#include <cstdint>

#define NN   32
#define WH   4096
#define CC   256
#define SCALE 0.0625f      // 1/sqrt(256)
#define BSCALE 64.0f       // pre-scale on B to keep folded ca*W in fp16 normal range
#define INV_BSCALE 0.015625f

// Scratch (device globals — no allocations allowed)
__device__ float g_q[NN * CC];
__device__ float g_partS[NN * 16 * CC];
__device__ float g_palog[NN * WH];
__device__ float g_ca[NN * CC];
__device__ float g_pa[NN * WH];
__device__ __align__(16) unsigned short g_Ah[(size_t)NN * WH * CC]; // fp16(inputs)
__device__ __align__(16) unsigned short g_Wh[CC * CC];              // fp16(W^T) [co][ci]
__device__ __align__(16) unsigned short g_Bh[NN * CC * CC];         // per-batch 64*ca*W

// ---------------------------------------------------------------------------
// Helpers (baseline PTX — plain sm_103 target)
// ---------------------------------------------------------------------------
__device__ __forceinline__ void ldm4(uint32_t* r, uint32_t addr) {
    asm volatile("ldmatrix.sync.aligned.m8n8.x4.shared.b16 {%0,%1,%2,%3}, [%4];"
                 : "=r"(r[0]), "=r"(r[1]), "=r"(r[2]), "=r"(r[3]) : "r"(addr));
}
__device__ __forceinline__ void mma_f16(float* c, const uint32_t* a,
                                        uint32_t b0, uint32_t b1) {
    asm volatile(
        "mma.sync.aligned.m16n8k16.row.col.f32.f16.f16.f32 "
        "{%0,%1,%2,%3}, {%4,%5,%6,%7}, {%8,%9}, {%0,%1,%2,%3};"
        : "+f"(c[0]), "+f"(c[1]), "+f"(c[2]), "+f"(c[3])
        : "r"(a[0]), "r"(a[1]), "r"(a[2]), "r"(a[3]), "r"(b0), "r"(b1));
}
__device__ __forceinline__ uint32_t pack_h2(float a, float b) {
    __half2 t = __floats2half2_rn(a, b);
    return *reinterpret_cast<uint32_t*>(&t);
}
__device__ __forceinline__ void cp16(uint32_t dst, const void* src) {
    asm volatile("cp.async.cg.shared.global [%0], [%1], 16;"
                 :: "r"(dst), "l"(src) : "memory");
}

// ---------------------------------------------------------------------------
// K1: q[n,c] = leaky_relu_0.3( style @ w_dense )
// ---------------------------------------------------------------------------
__global__ void k_q(const float* __restrict__ style, const float* __restrict__ wd) {
    int n = blockIdx.x, c = threadIdx.x;
    __shared__ float s[CC];
    s[c] = style[n * CC + c];
    __syncthreads();
    float acc = 0.f;
#pragma unroll 8
    for (int k = 0; k < CC; k++) acc = fmaf(s[k], wd[k * CC + c], acc);
    g_q[n * CC + c] = acc > 0.f ? acc : 0.3f * acc;
}

// ---------------------------------------------------------------------------
// K_wh: tiled transpose wc[ci][co] fp32 -> g_Wh[co][ci] fp16. grid(8,8), 256 thr.
// ---------------------------------------------------------------------------
__global__ void k_wh(const float* __restrict__ wc) {
    __shared__ float tile[32][33];
    int tx = threadIdx.x & 31, ty = threadIdx.x >> 5;
    int ci0 = blockIdx.y * 32, co0 = blockIdx.x * 32;
#pragma unroll
    for (int j = 0; j < 4; j++)
        tile[ty + j * 8][tx] = wc[(size_t)(ci0 + ty + j * 8) * CC + co0 + tx];
    __syncthreads();
#pragma unroll
    for (int j = 0; j < 4; j++) {
        int co = co0 + ty + j * 8;
        g_Wh[(size_t)co * CC + ci0 + tx] =
            __half_as_ushort(__float2half_rn(tile[tx][ty + j * 8]));
    }
}

// ---------------------------------------------------------------------------
// K2: one pass over inputs: pa_logits + partial column sums + fp16 copy of A
// ---------------------------------------------------------------------------
__global__ void k_pa_colsum(const float* __restrict__ in) {
    int n = blockIdx.y, chunk = blockIdx.x;
    int tid = threadIdx.x, lane = tid & 31, w = tid >> 5;

    const float4* q4 = reinterpret_cast<const float4*>(g_q + (size_t)n * CC);
    float4 qa = q4[lane * 2], qb = q4[lane * 2 + 1];

    float4 cs0 = {0.f, 0.f, 0.f, 0.f}, cs1 = {0.f, 0.f, 0.f, 0.f};
    int pbase = chunk * 256 + w * 32;
    const float4* base4 =
        reinterpret_cast<const float4*>(in + ((size_t)n * WH + pbase) * CC);

    for (int i = 0; i < 32; i++) {
        const float4* r = base4 + (size_t)i * (CC / 4);
        float4 v0 = r[lane * 2], v1 = r[lane * 2 + 1];
        float d = v0.x * qa.x + v0.y * qa.y + v0.z * qa.z + v0.w * qa.w
                + v1.x * qb.x + v1.y * qb.y + v1.z * qb.z + v1.w * qb.w;
        cs0.x += v0.x; cs0.y += v0.y; cs0.z += v0.z; cs0.w += v0.w;
        cs1.x += v1.x; cs1.y += v1.y; cs1.z += v1.z; cs1.w += v1.w;
        uint4 hc;
        hc.x = pack_h2(v0.x, v0.y); hc.y = pack_h2(v0.z, v0.w);
        hc.z = pack_h2(v1.x, v1.y); hc.w = pack_h2(v1.z, v1.w);
        *reinterpret_cast<uint4*>(
            g_Ah + ((size_t)n * WH + pbase + i) * CC + lane * 8) = hc;
#pragma unroll
        for (int o = 16; o; o >>= 1) d += __shfl_xor_sync(0xffffffffu, d, o);
        if (lane == 0) g_palog[(size_t)n * WH + pbase + i] = d * SCALE;
    }

    __shared__ float sm[8 * CC];
    float* smw = sm + w * CC + lane * 8;
    smw[0] = cs0.x; smw[1] = cs0.y; smw[2] = cs0.z; smw[3] = cs0.w;
    smw[4] = cs1.x; smw[5] = cs1.y; smw[6] = cs1.z; smw[7] = cs1.w;
    __syncthreads();
    float ssum = 0.f;
#pragma unroll
    for (int ww = 0; ww < 8; ww++) ssum += sm[ww * CC + tid];
    g_partS[((size_t)n * 16 + chunk) * CC + tid] = ssum;
}

// ---------------------------------------------------------------------------
// K3 (fused): blocks 0..31 -> channel softmax; 32..63 -> position softmax
// ---------------------------------------------------------------------------
__global__ void k_soft() {
    int b = blockIdx.x, tid = threadIdx.x;
    __shared__ float red[256];
    if (b < NN) {
        int n = b;
        float S = 0.f;
#pragma unroll
        for (int k = 0; k < 16; k++) S += g_partS[((size_t)n * 16 + k) * CC + tid];
        float logit = S * g_q[n * CC + tid] * SCALE;
        red[tid] = logit; __syncthreads();
        for (int s = 128; s; s >>= 1) {
            if (tid < s) red[tid] = fmaxf(red[tid], red[tid + s]);
            __syncthreads();
        }
        float m = red[0]; __syncthreads();
        float e = expf(logit - m);
        red[tid] = e; __syncthreads();
        for (int s = 128; s; s >>= 1) {
            if (tid < s) red[tid] += red[tid + s];
            __syncthreads();
        }
        g_ca[n * CC + tid] = e / red[0];
    } else {
        int n = b - NN;
        float v[16];
        float m = -1e30f;
#pragma unroll
        for (int i = 0; i < 16; i++) {
            v[i] = g_palog[(size_t)n * WH + i * 256 + tid];
            m = fmaxf(m, v[i]);
        }
        red[tid] = m; __syncthreads();
        for (int s = 128; s; s >>= 1) {
            if (tid < s) red[tid] = fmaxf(red[tid], red[tid + s]);
            __syncthreads();
        }
        m = red[0]; __syncthreads();
        float sum = 0.f;
#pragma unroll
        for (int i = 0; i < 16; i++) { v[i] = expf(v[i] - m); sum += v[i]; }
        red[tid] = sum; __syncthreads();
        for (int s = 128; s; s >>= 1) {
            if (tid < s) red[tid] += red[tid + s];
            __syncthreads();
        }
        float r = 1.f / red[0];
#pragma unroll
        for (int i = 0; i < 16; i++)
            g_pa[(size_t)n * WH + i * 256 + tid] = v[i] * r;
    }
}

// ---------------------------------------------------------------------------
// K_prepB: B_eff[n][co][ci] = fp16( 64 * ca[n][ci] * Wh[co][ci] ).
// Lane-mapped ci-fastest: 1 coalesced uint4 read + 1 coalesced uint4 write.
// grid=(32 co-blocks of 8, 32 n), block=256 (t>>5 = co row, t&31 = ci seg).
// ---------------------------------------------------------------------------
__global__ void k_prepB() {
    int n = blockIdx.y;
    int co = blockIdx.x * 8 + (threadIdx.x >> 5);
    int ci0 = (threadIdx.x & 31) * 8;
    uint4 w = *reinterpret_cast<const uint4*>(g_Wh + (size_t)co * CC + ci0);
    const float4* cap = reinterpret_cast<const float4*>(g_ca + n * CC + ci0);
    float4 c0 = cap[0], c1 = cap[1];
    const __half2* wh = reinterpret_cast<const __half2*>(&w);
    uint4 o;
    float2 f;
    f = __half22float2(wh[0]);
    o.x = pack_h2(BSCALE * c0.x * f.x, BSCALE * c0.y * f.y);
    f = __half22float2(wh[1]);
    o.y = pack_h2(BSCALE * c0.z * f.x, BSCALE * c0.w * f.y);
    f = __half22float2(wh[2]);
    o.z = pack_h2(BSCALE * c1.x * f.x, BSCALE * c1.y * f.y);
    f = __half22float2(wh[3]);
    o.w = pack_h2(BSCALE * c1.z * f.x, BSCALE * c1.w * f.y);
    *reinterpret_cast<uint4*>(g_Bh + ((size_t)n * CC + co) * CC + ci0) = o;
}

// ---------------------------------------------------------------------------
// K4: HMMA fp16 GEMM, CTA tile 128x128, warp tile 32x64, 2 CTAs/SM.
// 3-buffer pipeline, ONE __syncthreads per chunk (4 total): issue(c+2) after
// the sync is race-free (buf (c+2)%3's readers finished at compute(c-1)).
// Epilogue: leaky0.1 * pa/64. grid=(32 mtiles, 2 ntiles, 32 batch), block=256.
// ---------------------------------------------------------------------------
#define RS     144                   // smem row stride bytes (64 halves + 8 pad)
#define A_OFF  0
#define B_OFF  18432                 // 128 * 144
#define BUFB   36864                 // A + B
#define SMEMB  (3 * BUFB)            // 110592 per CTA -> 221184 per SM @2 CTAs

__global__ void __launch_bounds__(256, 2)
k_conv_mma(float* __restrict__ out) {
    extern __shared__ char smem[];
    const uint32_t sb = (uint32_t)__cvta_generic_to_shared(smem);
    const int tid = threadIdx.x, lane = tid & 31, wid = tid >> 5;
    const int nb = blockIdx.z;
    const int m0 = blockIdx.x * 128;
    const int n0 = blockIdx.y * 128;
    const int warp_m = (wid & 3) * 32, warp_n = (wid >> 2) * 64;
    const int q = lane >> 3;

    const uint32_t aBase = sb + A_OFF
        + (uint32_t)(warp_m + (lane & 7) + ((q & 1) << 3)) * RS + ((q >> 1) << 4);
    const uint32_t bBase = sb + B_OFF
        + (uint32_t)(warp_n + (lane & 7) + ((q >> 1) << 3)) * RS + ((q & 1) << 4);

    const unsigned short* Asrc = g_Ah + ((size_t)nb * WH + m0) * CC;
    const unsigned short* Bsrc = g_Bh + ((size_t)nb * CC + n0) * CC;

    float acc[2][8][4];
#pragma unroll
    for (int i = 0; i < 2; i++)
#pragma unroll
        for (int j = 0; j < 8; j++)
#pragma unroll
            for (int t = 0; t < 4; t++) acc[i][j][t] = 0.f;

    // chunk c covers k in [c*64, c*64+64): A/B each 128 rows x 8 segs of 16B.
    auto issue = [&](int c, int buf) {
        uint32_t d = sb + (uint32_t)buf * BUFB;
#pragma unroll
        for (int j = 0; j < 4; j++) {
            int o = tid + 256 * j, row = o >> 3, seg = o & 7;
            cp16(d + A_OFF + row * RS + seg * 16,
                 Asrc + (size_t)row * CC + c * 64 + seg * 8);
        }
#pragma unroll
        for (int j = 0; j < 4; j++) {
            int o = tid + 256 * j, row = o >> 3, seg = o & 7;
            cp16(d + B_OFF + row * RS + seg * 16,
                 Bsrc + (size_t)row * CC + c * 64 + seg * 8);
        }
        asm volatile("cp.async.commit_group;" ::: "memory");
    };

    issue(0, 0);
    issue(1, 1);
#pragma unroll
    for (int c = 0; c < 4; c++) {
        if (c < 3)
            asm volatile("cp.async.wait_group 1;" ::: "memory");
        else
            asm volatile("cp.async.wait_group 0;" ::: "memory");
        __syncthreads();
        if (c + 2 < 4) issue(c + 2, (c + 2) % 3);

        const uint32_t bo = (uint32_t)(c % 3) * BUFB;
#pragma unroll
        for (int ks = 0; ks < 4; ks++) {
            const uint32_t ko = bo + ks * 32;
            uint32_t ah[2][4];
            ldm4(ah[0], aBase + ko);
            ldm4(ah[1], aBase + ko + 16 * RS);
#pragma unroll
            for (int p = 0; p < 4; p++) {
                uint32_t bh[4];
                ldm4(bh, bBase + ko + p * 16 * RS);
                mma_f16(acc[0][2 * p],     ah[0], bh[0], bh[1]);
                mma_f16(acc[0][2 * p + 1], ah[0], bh[2], bh[3]);
                mma_f16(acc[1][2 * p],     ah[1], bh[0], bh[1]);
                mma_f16(acc[1][2 * p + 1], ah[1], bh[2], bh[3]);
            }
        }
    }

    // --- Epilogue: leaky0.1 then * pa/64 (undo BSCALE; leaky is +homogeneous) ---
    const int g = lane >> 2, tg = lane & 3;
#pragma unroll
    for (int mt = 0; mt < 2; mt++) {
        int r0 = m0 + warp_m + mt * 16 + g;
        float pa0 = g_pa[(size_t)nb * WH + r0] * INV_BSCALE;
        float pa1 = g_pa[(size_t)nb * WH + r0 + 8] * INV_BSCALE;
        float* o0 = out + ((size_t)nb * WH + r0) * CC + n0 + warp_n + tg * 2;
        float* o1 = o0 + 8 * CC;
#pragma unroll
        for (int nt = 0; nt < 8; nt++) {
            float v0 = acc[mt][nt][0], v1 = acc[mt][nt][1];
            float v2 = acc[mt][nt][2], v3 = acc[mt][nt][3];
            v0 = (v0 > 0.f ? v0 : 0.1f * v0) * pa0;
            v1 = (v1 > 0.f ? v1 : 0.1f * v1) * pa0;
            v2 = (v2 > 0.f ? v2 : 0.1f * v2) * pa1;
            v3 = (v3 > 0.f ? v3 : 0.1f * v3) * pa1;
            *reinterpret_cast<float2*>(o0 + nt * 8) = make_float2(v0, v1);
            *reinterpret_cast<float2*>(o1 + nt * 8) = make_float2(v2, v3);
        }
    }
}

// ---------------------------------------------------------------------------
extern "C" void kernel_launch(void* const* d_in, const int* in_sizes, int n_in,
                              void* d_out, int out_size) {
    const float* in    = (const float*)d_in[0];  // [32,64,64,256]
    const float* style = (const float*)d_in[1];  // [32,256]
    const float* wd    = (const float*)d_in[2];  // [256,256]
    const float* wc    = (const float*)d_in[3];  // [1,1,256,256] -> [ci][co]
    float* out = (float*)d_out;

    static bool attr_set = false;
    if (!attr_set) {
        cudaFuncSetAttribute(k_conv_mma,
                             cudaFuncAttributeMaxDynamicSharedMemorySize, SMEMB);
        attr_set = true;
    }

    k_q<<<NN, CC>>>(style, wd);
    k_wh<<<dim3(8, 8), 256>>>(wc);
    k_pa_colsum<<<dim3(16, NN), 256>>>(in);
    k_soft<<<2 * NN, 256>>>();
    k_prepB<<<dim3(32, NN), 256>>>();
    k_conv_mma<<<dim3(32, 2, NN), 256, SMEMB>>>(out);
}